// round 11
// baseline (speedup 1.0000x reference)
#include <cuda_runtime.h>
#include <cuda_bf16.h>
#include <cstdint>

// ---------------------------------------------------------------------------
// MHA: x[4,2048,1024] -> QKV gemm -> 16-head flash attention -> proj gemm
// fp32 SIMT with packed fma.rn.f32x2 (Blackwell FFMA2) everywhere.
// ---------------------------------------------------------------------------

#define B_   4
#define T_   2048
#define D_   1024
#define H_   16
#define DK_  64
#define M_   (B_ * T_)          // 8192

// Scratch (allocation-free rule: __device__ globals)
__device__ float g_Q[B_ * H_ * T_ * DK_];   // 32 MB, pre-scaled by 1/sqrt(dk)
__device__ float g_K[B_ * H_ * T_ * DK_];
__device__ float g_V[B_ * H_ * T_ * DK_];
__device__ float g_O[B_ * T_ * D_];         // attention output, [B,T,D]

typedef unsigned long long ull;

__device__ __forceinline__ ull pack2(float x, float y) {
    ull r; asm("mov.b64 %0, {%1,%2};" : "=l"(r) : "f"(x), "f"(y)); return r;
}
__device__ __forceinline__ void unpack2(ull v, float &x, float &y) {
    asm("mov.b64 {%0,%1}, %2;" : "=f"(x), "=f"(y) : "l"(v));
}
// d = a*b + d on packed f32x2 (FFMA2)
__device__ __forceinline__ void fma2(ull &d, ull a, ull b) {
    asm("fma.rn.f32x2 %0, %1, %2, %0;" : "+l"(d) : "l"(a), "l"(b));
}
__device__ __forceinline__ void mul2(ull &d, ull a) {
    asm("mul.rn.f32x2 %0, %0, %1;" : "+l"(d) : "l"(a));
}

// ---------------------------------------------------------------------------
// Generic TN GEMM: C[M,N] = A[M,K] @ Bw[N,K]^T
// BM=BN=128, BK=16, 256 threads, 8x8 per thread (packed into 8x4 f32x2 accums)
// mode 0: A = x, scatter C into g_Q/g_K/g_V head layout (Q scaled by 0.125)
// mode 1: A = g_O, write C to out
// ---------------------------------------------------------------------------
__global__ __launch_bounds__(256, 2)
void gemm_tn_kernel(const float* __restrict__ A, const float* __restrict__ Bw,
                    float* __restrict__ out, int M, int N, int K, int mode)
{
    __shared__ __align__(16) float As[16][132];
    __shared__ __align__(16) float Bs[16][132];

    const float* __restrict__ Ap = (mode == 1) ? (const float*)g_O : A;

    const int m0 = blockIdx.y * 128;
    const int n0 = blockIdx.x * 128;
    const int tid = threadIdx.x;
    const int ttx = tid & 15;       // column block (8 cols)
    const int tty = tid >> 4;       // row block    (8 rows)

    ull acc[8][4];
#pragma unroll
    for (int i = 0; i < 8; i++)
#pragma unroll
        for (int j = 0; j < 4; j++) acc[i][j] = 0ull;

    for (int k0 = 0; k0 < K; k0 += 16) {
        __syncthreads();
#pragma unroll
        for (int i = 0; i < 2; i++) {
            int v  = tid + i * 256;      // 0..511
            int r  = v >> 2;             // 0..127
            int c4 = (v & 3) * 4;        // 0,4,8,12
            float4 av = *(const float4*)(Ap + (size_t)(m0 + r) * K + k0 + c4);
            As[c4 + 0][r] = av.x; As[c4 + 1][r] = av.y;
            As[c4 + 2][r] = av.z; As[c4 + 3][r] = av.w;
            float4 bv = *(const float4*)(Bw + (size_t)(n0 + r) * K + k0 + c4);
            Bs[c4 + 0][r] = bv.x; Bs[c4 + 1][r] = bv.y;
            Bs[c4 + 2][r] = bv.z; Bs[c4 + 3][r] = bv.w;
        }
        __syncthreads();

#pragma unroll
        for (int k = 0; k < 16; k++) {
            float4 a0 = *(const float4*)&As[k][tty * 8];
            float4 a1 = *(const float4*)&As[k][tty * 8 + 4];
            float4 b0 = *(const float4*)&Bs[k][ttx * 8];
            float4 b1 = *(const float4*)&Bs[k][ttx * 8 + 4];
            ull bb0 = pack2(b0.x, b0.y), bb1 = pack2(b0.z, b0.w);
            ull bb2 = pack2(b1.x, b1.y), bb3 = pack2(b1.z, b1.w);
            float av[8] = {a0.x, a0.y, a0.z, a0.w, a1.x, a1.y, a1.z, a1.w};
#pragma unroll
            for (int i = 0; i < 8; i++) {
                ull ad = pack2(av[i], av[i]);
                fma2(acc[i][0], ad, bb0);
                fma2(acc[i][1], ad, bb1);
                fma2(acc[i][2], ad, bb2);
                fma2(acc[i][3], ad, bb3);
            }
        }
    }

#pragma unroll
    for (int i = 0; i < 8; i++) {
        float c[8];
        unpack2(acc[i][0], c[0], c[1]); unpack2(acc[i][1], c[2], c[3]);
        unpack2(acc[i][2], c[4], c[5]); unpack2(acc[i][3], c[6], c[7]);
        int m = m0 + tty * 8 + i;
        if (mode == 0) {
            int b = m >> 11, t = m & 2047;
#pragma unroll
            for (int j = 0; j < 8; j++) {
                int n = n0 + ttx * 8 + j;
                int which = n >> 10;
                int rem = n & 1023;
                int h = rem >> 6, dd = rem & 63;
                size_t idx = ((size_t)((b << 4) + h) * T_ + t) * DK_ + dd;
                if (which == 0)       g_Q[idx] = c[j] * 0.125f;  // 1/sqrt(64)
                else if (which == 1)  g_K[idx] = c[j];
                else                  g_V[idx] = c[j];
            }
        } else {
            float* o = out + (size_t)m * N + n0 + ttx * 8;
            *(float4*)(o)     = make_float4(c[0], c[1], c[2], c[3]);
            *(float4*)(o + 4) = make_float4(c[4], c[5], c[6], c[7]);
        }
    }
}

// ---------------------------------------------------------------------------
// Flash attention: one block per (bh, 128-row Q tile). Bc = 64 keys per step.
// SMEM: Qs[128][68] rowmajor | Kt[64(d)][68] transposed | Vs[64][68] rowmajor
//       Ps[128][68] rowmajor.  Thread grid 16x16: 8 rows x 4 cols per thread.
// ---------------------------------------------------------------------------
#define QS_OFF 0
#define KT_OFF 8704                  // 128*68
#define VS_OFF (8704 + 4352)         // + 64*68
#define PS_OFF (8704 + 4352 + 4352)
#define ATTN_SMEM_FLOATS (8704 + 4352 + 4352 + 8704)
#define ATTN_SMEM_BYTES  (ATTN_SMEM_FLOATS * 4)   // 104448

__global__ __launch_bounds__(256, 2)
void attn_kernel()
{
    extern __shared__ __align__(16) float sm[];
    float* Qs = sm + QS_OFF;
    float* Kt = sm + KT_OFF;
    float* Vs = sm + VS_OFF;
    float* Ps = sm + PS_OFF;

    const int qt = blockIdx.x;       // 0..15
    const int bh = blockIdx.y;       // 0..63
    const float* __restrict__ Qg = g_Q + (size_t)bh * (T_ * DK_) + (size_t)qt * (128 * DK_);
    const float* __restrict__ Kg = g_K + (size_t)bh * (T_ * DK_);
    const float* __restrict__ Vg = g_V + (size_t)bh * (T_ * DK_);

    const int tid = threadIdx.x;
    const int ttx = tid & 15;        // 4 cols each
    const int tty = tid >> 4;        // 8 rows each

    // Load Q tile (128x64) once
#pragma unroll
    for (int i = 0; i < 8; i++) {
        int v  = tid + i * 256;
        int r  = v >> 4;
        int c4 = (v & 15) * 4;
        *(float4*)&Qs[r * 68 + c4] = *(const float4*)(Qg + r * 64 + c4);
    }

    ull O2[8][2];
    float mrow[8], lrow[8];
#pragma unroll
    for (int i = 0; i < 8; i++) {
        O2[i][0] = 0ull; O2[i][1] = 0ull;
        mrow[i] = -1e30f; lrow[i] = 0.0f;
    }

    for (int kt = 0; kt < T_ / 64; kt++) {
        __syncthreads();   // previous PV reads of Vs/Ps done
        // Load K (transposed) and V tiles, 64x64 each
#pragma unroll
        for (int i = 0; i < 4; i++) {
            int v  = tid + i * 256;
            int r  = v >> 4;             // key index 0..63
            int c4 = (v & 15) * 4;       // d
            float4 kk = *(const float4*)(Kg + kt * 4096 + r * 64 + c4);
            Kt[(c4 + 0) * 68 + r] = kk.x;
            Kt[(c4 + 1) * 68 + r] = kk.y;
            Kt[(c4 + 2) * 68 + r] = kk.z;
            Kt[(c4 + 3) * 68 + r] = kk.w;
            *(float4*)&Vs[r * 68 + c4] = *(const float4*)(Vg + kt * 4096 + r * 64 + c4);
        }
        __syncthreads();

        // S = Q @ K^T, per-thread 8 rows x 4 cols (packed 8x2)
        ull s2[8][2];
#pragma unroll
        for (int i = 0; i < 8; i++) { s2[i][0] = 0ull; s2[i][1] = 0ull; }
#pragma unroll 8
        for (int d = 0; d < 64; d++) {
            float4 kv = *(const float4*)&Kt[d * 68 + ttx * 4];
            ull b0 = pack2(kv.x, kv.y), b1 = pack2(kv.z, kv.w);
#pragma unroll
            for (int i = 0; i < 8; i++) {
                float a = Qs[(tty * 8 + i) * 68 + d];
                ull ad = pack2(a, a);
                fma2(s2[i][0], ad, b0);
                fma2(s2[i][1], ad, b1);
            }
        }

        // Online softmax per row; write P to SMEM
#pragma unroll
        for (int i = 0; i < 8; i++) {
            float p0, p1, p2, p3;
            unpack2(s2[i][0], p0, p1);
            unpack2(s2[i][1], p2, p3);
            float v = fmaxf(fmaxf(p0, p1), fmaxf(p2, p3));
            v = fmaxf(v, __shfl_xor_sync(0xffffffffu, v, 8));
            v = fmaxf(v, __shfl_xor_sync(0xffffffffu, v, 4));
            v = fmaxf(v, __shfl_xor_sync(0xffffffffu, v, 2));
            v = fmaxf(v, __shfl_xor_sync(0xffffffffu, v, 1));
            float mn = fmaxf(mrow[i], v);
            float alpha = __expf(mrow[i] - mn);
            mrow[i] = mn;
            p0 = __expf(p0 - mn); p1 = __expf(p1 - mn);
            p2 = __expf(p2 - mn); p3 = __expf(p3 - mn);
            float rs = (p0 + p1) + (p2 + p3);
            rs += __shfl_xor_sync(0xffffffffu, rs, 8);
            rs += __shfl_xor_sync(0xffffffffu, rs, 4);
            rs += __shfl_xor_sync(0xffffffffu, rs, 2);
            rs += __shfl_xor_sync(0xffffffffu, rs, 1);
            lrow[i] = lrow[i] * alpha + rs;
            ull am = pack2(alpha, alpha);
            mul2(O2[i][0], am);
            mul2(O2[i][1], am);
            *(float4*)&Ps[(tty * 8 + i) * 68 + ttx * 4] = make_float4(p0, p1, p2, p3);
        }
        __syncthreads();

        // O += P @ V
#pragma unroll 8
        for (int j = 0; j < 64; j++) {
            float4 vv = *(const float4*)&Vs[j * 68 + ttx * 4];
            ull b0 = pack2(vv.x, vv.y), b1 = pack2(vv.z, vv.w);
#pragma unroll
            for (int i = 0; i < 8; i++) {
                float a = Ps[(tty * 8 + i) * 68 + j];
                ull ad = pack2(a, a);
                fma2(O2[i][0], ad, b0);
                fma2(O2[i][1], ad, b1);
            }
        }
    }

    // Normalize and store to g_O in [B,T,D] layout
    const int b = bh >> 4, h = bh & 15;
#pragma unroll
    for (int i = 0; i < 8; i++) {
        float o0, o1, o2, o3;
        unpack2(O2[i][0], o0, o1);
        unpack2(O2[i][1], o2, o3);
        float inv = 1.0f / lrow[i];
        int t = qt * 128 + tty * 8 + i;
        *(float4*)&g_O[((size_t)(b * T_ + t)) * D_ + h * 64 + ttx * 4]
            = make_float4(o0 * inv, o1 * inv, o2 * inv, o3 * inv);
    }
}

// ---------------------------------------------------------------------------
extern "C" void kernel_launch(void* const* d_in, const int* in_sizes, int n_in,
                              void* d_out, int out_size)
{
    const float* x      = (const float*)d_in[0];   // [4,2048,1024]
    const float* W_qkv  = (const float*)d_in[1];   // [3072,1024]
    const float* W_proj = (const float*)d_in[2];   // [1024,1024]
    float* out = (float*)d_out;                    // [4,2048,1024]

    cudaFuncSetAttribute(attn_kernel,
                         cudaFuncAttributeMaxDynamicSharedMemorySize,
                         ATTN_SMEM_BYTES);

    // 1) QKV GEMM + head-layout scatter (Q pre-scaled)
    dim3 g1(3 * D_ / 128, M_ / 128);   // (24, 64)
    gemm_tn_kernel<<<g1, 256>>>(x, W_qkv, nullptr, M_, 3 * D_, D_, 0);

    // 2) Flash attention
    dim3 g2(T_ / 128, B_ * H_);        // (16, 64)
    attn_kernel<<<g2, 256, ATTN_SMEM_BYTES>>>();

    // 3) Output projection
    dim3 g3(D_ / 128, M_ / 128);       // (8, 64)
    gemm_tn_kernel<<<g3, 256>>>(nullptr, W_proj, out, M_, D_, D_, 1);
}

// round 12
// speedup vs baseline: 1.0005x; 1.0005x over previous
#include <cuda_runtime.h>
#include <cuda_bf16.h>
#include <cstdint>

// ---------------------------------------------------------------------------
// MHA: x[4,2048,1024] -> QKV gemm -> 16-head flash attention -> proj gemm
// fp32 SIMT with packed fma.rn.f32x2 (Blackwell FFMA2) everywhere.
// ---------------------------------------------------------------------------

#define B_   4
#define T_   2048
#define D_   1024
#define H_   16
#define DK_  64
#define M_   (B_ * T_)          // 8192

// Scratch (allocation-free rule: __device__ globals)
__device__ float g_Q[B_ * H_ * T_ * DK_];   // 32 MB, pre-scaled by 1/sqrt(dk)
__device__ float g_K[B_ * H_ * T_ * DK_];
__device__ float g_V[B_ * H_ * T_ * DK_];
__device__ float g_O[B_ * T_ * D_];         // attention output, [B,T,D]

typedef unsigned long long ull;

__device__ __forceinline__ ull pack2(float x, float y) {
    ull r; asm("mov.b64 %0, {%1,%2};" : "=l"(r) : "f"(x), "f"(y)); return r;
}
__device__ __forceinline__ void unpack2(ull v, float &x, float &y) {
    asm("mov.b64 {%0,%1}, %2;" : "=f"(x), "=f"(y) : "l"(v));
}
// d = a*b + d on packed f32x2 (FFMA2)
__device__ __forceinline__ void fma2(ull &d, ull a, ull b) {
    asm("fma.rn.f32x2 %0, %1, %2, %0;" : "+l"(d) : "l"(a), "l"(b));
}
__device__ __forceinline__ void mul2(ull &d, ull a) {
    asm("mul.rn.f32x2 %0, %0, %1;" : "+l"(d) : "l"(a));
}

// ---------------------------------------------------------------------------
// Generic TN GEMM: C[M,N] = A[M,K] @ Bw[N,K]^T
// BM=BN=128, BK=16, 256 threads, 8x8 per thread (packed into 8x4 f32x2 accums)
// mode 0: A = x, scatter C into g_Q/g_K/g_V head layout (Q scaled by 0.125)
// mode 1: A = g_O, write C to out
// ---------------------------------------------------------------------------
__global__ __launch_bounds__(256, 2)
void gemm_tn_kernel(const float* __restrict__ A, const float* __restrict__ Bw,
                    float* __restrict__ out, int M, int N, int K, int mode)
{
    __shared__ __align__(16) float As[16][132];
    __shared__ __align__(16) float Bs[16][132];

    const float* __restrict__ Ap = (mode == 1) ? (const float*)g_O : A;

    const int m0 = blockIdx.y * 128;
    const int n0 = blockIdx.x * 128;
    const int tid = threadIdx.x;
    const int ttx = tid & 15;       // column block (8 cols)
    const int tty = tid >> 4;       // row block    (8 rows)

    ull acc[8][4];
#pragma unroll
    for (int i = 0; i < 8; i++)
#pragma unroll
        for (int j = 0; j < 4; j++) acc[i][j] = 0ull;

    for (int k0 = 0; k0 < K; k0 += 16) {
        __syncthreads();
#pragma unroll
        for (int i = 0; i < 2; i++) {
            int v  = tid + i * 256;      // 0..511
            int r  = v >> 2;             // 0..127
            int c4 = (v & 3) * 4;        // 0,4,8,12
            float4 av = *(const float4*)(Ap + (size_t)(m0 + r) * K + k0 + c4);
            As[c4 + 0][r] = av.x; As[c4 + 1][r] = av.y;
            As[c4 + 2][r] = av.z; As[c4 + 3][r] = av.w;
            float4 bv = *(const float4*)(Bw + (size_t)(n0 + r) * K + k0 + c4);
            Bs[c4 + 0][r] = bv.x; Bs[c4 + 1][r] = bv.y;
            Bs[c4 + 2][r] = bv.z; Bs[c4 + 3][r] = bv.w;
        }
        __syncthreads();

#pragma unroll
        for (int k = 0; k < 16; k++) {
            float4 a0 = *(const float4*)&As[k][tty * 8];
            float4 a1 = *(const float4*)&As[k][tty * 8 + 4];
            float4 b0 = *(const float4*)&Bs[k][ttx * 8];
            float4 b1 = *(const float4*)&Bs[k][ttx * 8 + 4];
            ull bb0 = pack2(b0.x, b0.y), bb1 = pack2(b0.z, b0.w);
            ull bb2 = pack2(b1.x, b1.y), bb3 = pack2(b1.z, b1.w);
            float av[8] = {a0.x, a0.y, a0.z, a0.w, a1.x, a1.y, a1.z, a1.w};
#pragma unroll
            for (int i = 0; i < 8; i++) {
                ull ad = pack2(av[i], av[i]);
                fma2(acc[i][0], ad, bb0);
                fma2(acc[i][1], ad, bb1);
                fma2(acc[i][2], ad, bb2);
                fma2(acc[i][3], ad, bb3);
            }
        }
    }

#pragma unroll
    for (int i = 0; i < 8; i++) {
        float c[8];
        unpack2(acc[i][0], c[0], c[1]); unpack2(acc[i][1], c[2], c[3]);
        unpack2(acc[i][2], c[4], c[5]); unpack2(acc[i][3], c[6], c[7]);
        int m = m0 + tty * 8 + i;
        if (mode == 0) {
            int b = m >> 11, t = m & 2047;
#pragma unroll
            for (int j = 0; j < 8; j++) {
                int n = n0 + ttx * 8 + j;
                int which = n >> 10;
                int rem = n & 1023;
                int h = rem >> 6, dd = rem & 63;
                size_t idx = ((size_t)((b << 4) + h) * T_ + t) * DK_ + dd;
                if (which == 0)       g_Q[idx] = c[j] * 0.125f;  // 1/sqrt(64)
                else if (which == 1)  g_K[idx] = c[j];
                else                  g_V[idx] = c[j];
            }
        } else {
            float* o = out + (size_t)m * N + n0 + ttx * 8;
            *(float4*)(o)     = make_float4(c[0], c[1], c[2], c[3]);
            *(float4*)(o + 4) = make_float4(c[4], c[5], c[6], c[7]);
        }
    }
}

// ---------------------------------------------------------------------------
// Flash attention: one block per (bh, 128-row Q tile). Bc = 64 keys per step.
// SMEM: Qs[128][68] rowmajor | Kt[64(d)][68] transposed | Vs[64][68] rowmajor
//       Ps[128][68] rowmajor.  Thread grid 16x16: 8 rows x 4 cols per thread.
// ---------------------------------------------------------------------------
#define QS_OFF 0
#define KT_OFF 8704                  // 128*68
#define VS_OFF (8704 + 4352)         // + 64*68
#define PS_OFF (8704 + 4352 + 4352)
#define ATTN_SMEM_FLOATS (8704 + 4352 + 4352 + 8704)
#define ATTN_SMEM_BYTES  (ATTN_SMEM_FLOATS * 4)   // 104448

__global__ __launch_bounds__(256, 2)
void attn_kernel()
{
    extern __shared__ __align__(16) float sm[];
    float* Qs = sm + QS_OFF;
    float* Kt = sm + KT_OFF;
    float* Vs = sm + VS_OFF;
    float* Ps = sm + PS_OFF;

    const int qt = blockIdx.x;       // 0..15
    const int bh = blockIdx.y;       // 0..63
    const float* __restrict__ Qg = g_Q + (size_t)bh * (T_ * DK_) + (size_t)qt * (128 * DK_);
    const float* __restrict__ Kg = g_K + (size_t)bh * (T_ * DK_);
    const float* __restrict__ Vg = g_V + (size_t)bh * (T_ * DK_);

    const int tid = threadIdx.x;
    const int ttx = tid & 15;        // 4 cols each
    const int tty = tid >> 4;        // 8 rows each

    // Load Q tile (128x64) once
#pragma unroll
    for (int i = 0; i < 8; i++) {
        int v  = tid + i * 256;
        int r  = v >> 4;
        int c4 = (v & 15) * 4;
        *(float4*)&Qs[r * 68 + c4] = *(const float4*)(Qg + r * 64 + c4);
    }

    ull O2[8][2];
    float mrow[8], lrow[8];
#pragma unroll
    for (int i = 0; i < 8; i++) {
        O2[i][0] = 0ull; O2[i][1] = 0ull;
        mrow[i] = -1e30f; lrow[i] = 0.0f;
    }

    for (int kt = 0; kt < T_ / 64; kt++) {
        __syncthreads();   // previous PV reads of Vs/Ps done
        // Load K (transposed) and V tiles, 64x64 each
#pragma unroll
        for (int i = 0; i < 4; i++) {
            int v  = tid + i * 256;
            int r  = v >> 4;             // key index 0..63
            int c4 = (v & 15) * 4;       // d
            float4 kk = *(const float4*)(Kg + kt * 4096 + r * 64 + c4);
            Kt[(c4 + 0) * 68 + r] = kk.x;
            Kt[(c4 + 1) * 68 + r] = kk.y;
            Kt[(c4 + 2) * 68 + r] = kk.z;
            Kt[(c4 + 3) * 68 + r] = kk.w;
            *(float4*)&Vs[r * 68 + c4] = *(const float4*)(Vg + kt * 4096 + r * 64 + c4);
        }
        __syncthreads();

        // S = Q @ K^T, per-thread 8 rows x 4 cols (packed 8x2)
        ull s2[8][2];
#pragma unroll
        for (int i = 0; i < 8; i++) { s2[i][0] = 0ull; s2[i][1] = 0ull; }
#pragma unroll 8
        for (int d = 0; d < 64; d++) {
            float4 kv = *(const float4*)&Kt[d * 68 + ttx * 4];
            ull b0 = pack2(kv.x, kv.y), b1 = pack2(kv.z, kv.w);
#pragma unroll
            for (int i = 0; i < 8; i++) {
                float a = Qs[(tty * 8 + i) * 68 + d];
                ull ad = pack2(a, a);
                fma2(s2[i][0], ad, b0);
                fma2(s2[i][1], ad, b1);
            }
        }

        // Online softmax per row; write P to SMEM
#pragma unroll
        for (int i = 0; i < 8; i++) {
            float p0, p1, p2, p3;
            unpack2(s2[i][0], p0, p1);
            unpack2(s2[i][1], p2, p3);
            float v = fmaxf(fmaxf(p0, p1), fmaxf(p2, p3));
            v = fmaxf(v, __shfl_xor_sync(0xffffffffu, v, 8));
            v = fmaxf(v, __shfl_xor_sync(0xffffffffu, v, 4));
            v = fmaxf(v, __shfl_xor_sync(0xffffffffu, v, 2));
            v = fmaxf(v, __shfl_xor_sync(0xffffffffu, v, 1));
            float mn = fmaxf(mrow[i], v);
            float alpha = __expf(mrow[i] - mn);
            mrow[i] = mn;
            p0 = __expf(p0 - mn); p1 = __expf(p1 - mn);
            p2 = __expf(p2 - mn); p3 = __expf(p3 - mn);
            float rs = (p0 + p1) + (p2 + p3);
            rs += __shfl_xor_sync(0xffffffffu, rs, 8);
            rs += __shfl_xor_sync(0xffffffffu, rs, 4);
            rs += __shfl_xor_sync(0xffffffffu, rs, 2);
            rs += __shfl_xor_sync(0xffffffffu, rs, 1);
            lrow[i] = lrow[i] * alpha + rs;
            ull am = pack2(alpha, alpha);
            mul2(O2[i][0], am);
            mul2(O2[i][1], am);
            *(float4*)&Ps[(tty * 8 + i) * 68 + ttx * 4] = make_float4(p0, p1, p2, p3);
        }
        __syncthreads();

        // O += P @ V
#pragma unroll 8
        for (int j = 0; j < 64; j++) {
            float4 vv = *(const float4*)&Vs[j * 68 + ttx * 4];
            ull b0 = pack2(vv.x, vv.y), b1 = pack2(vv.z, vv.w);
#pragma unroll
            for (int i = 0; i < 8; i++) {
                float a = Ps[(tty * 8 + i) * 68 + j];
                ull ad = pack2(a, a);
                fma2(O2[i][0], ad, b0);
                fma2(O2[i][1], ad, b1);
            }
        }
    }

    // Normalize and store to g_O in [B,T,D] layout
    const int b = bh >> 4, h = bh & 15;
#pragma unroll
    for (int i = 0; i < 8; i++) {
        float o0, o1, o2, o3;
        unpack2(O2[i][0], o0, o1);
        unpack2(O2[i][1], o2, o3);
        float inv = 1.0f / lrow[i];
        int t = qt * 128 + tty * 8 + i;
        *(float4*)&g_O[((size_t)(b * T_ + t)) * D_ + h * 64 + ttx * 4]
            = make_float4(o0 * inv, o1 * inv, o2 * inv, o3 * inv);
    }
}

// ---------------------------------------------------------------------------
extern "C" void kernel_launch(void* const* d_in, const int* in_sizes, int n_in,
                              void* d_out, int out_size)
{
    const float* x      = (const float*)d_in[0];   // [4,2048,1024]
    const float* W_qkv  = (const float*)d_in[1];   // [3072,1024]
    const float* W_proj = (const float*)d_in[2];   // [1024,1024]
    float* out = (float*)d_out;                    // [4,2048,1024]

    cudaFuncSetAttribute(attn_kernel,
                         cudaFuncAttributeMaxDynamicSharedMemorySize,
                         ATTN_SMEM_BYTES);

    // 1) QKV GEMM + head-layout scatter (Q pre-scaled)
    dim3 g1(3 * D_ / 128, M_ / 128);   // (24, 64)
    gemm_tn_kernel<<<g1, 256>>>(x, W_qkv, nullptr, M_, 3 * D_, D_, 0);

    // 2) Flash attention
    dim3 g2(T_ / 128, B_ * H_);        // (16, 64)
    attn_kernel<<<g2, 256, ATTN_SMEM_BYTES>>>();

    // 3) Output projection
    dim3 g3(D_ / 128, M_ / 128);       // (8, 64)
    gemm_tn_kernel<<<g3, 256>>>(nullptr, W_proj, out, M_, D_, D_, 1);
}

// round 13
// speedup vs baseline: 2.2401x; 2.2389x over previous
#include <cuda_runtime.h>
#include <cuda_bf16.h>
#include <cstdint>

// ---------------------------------------------------------------------------
// MHA via tf32 mma.sync (m16n8k8) everywhere.
// x[4,2048,1024] -> QKV gemm -> 16-head flash attention -> proj gemm
// ---------------------------------------------------------------------------

#define B_   4
#define T_   2048
#define D_   1024
#define H_   16
#define DK_  64
#define M_   (B_ * T_)          // 8192

// Scratch (allocation-free rule: __device__ globals)
__device__ float g_Q[B_ * H_ * T_ * DK_];   // pre-scaled by 1/sqrt(dk)
__device__ float g_K[B_ * H_ * T_ * DK_];
__device__ float g_V[B_ * H_ * T_ * DK_];
__device__ float g_O[B_ * T_ * D_];         // attention output, [B,T,D]

__device__ __forceinline__ uint32_t f2tf(float f) {
    uint32_t u; asm("cvt.rna.tf32.f32 %0, %1;" : "=r"(u) : "f"(f)); return u;
}

// D = A(16x8,row) * B(8x8,col) + D, tf32 in / f32 out
__device__ __forceinline__ void mma8(float c[4],
                                     uint32_t a0, uint32_t a1, uint32_t a2, uint32_t a3,
                                     uint32_t b0, uint32_t b1) {
    asm volatile("mma.sync.aligned.m16n8k8.row.col.f32.tf32.tf32.f32 "
                 "{%0,%1,%2,%3}, {%4,%5,%6,%7}, {%8,%9}, {%0,%1,%2,%3};"
                 : "+f"(c[0]), "+f"(c[1]), "+f"(c[2]), "+f"(c[3])
                 : "r"(a0), "r"(a1), "r"(a2), "r"(a3), "r"(b0), "r"(b1));
}

__device__ __forceinline__ void qkv_scatter(int m, int n, float c) {
    int b = m >> 11, t = m & 2047;
    int which = n >> 10, rem = n & 1023;
    int h = rem >> 6, dd = rem & 63;
    size_t idx = ((size_t)((b << 4) + h) * T_ + t) * DK_ + dd;
    if (which == 0)      g_Q[idx] = c * 0.125f;    // 1/sqrt(64)
    else if (which == 1) g_K[idx] = c;
    else                 g_V[idx] = c;
}

// ---------------------------------------------------------------------------
// TN GEMM: C[M,N] = A[M,K] @ Bw[N,K]^T.  BM=BN=128, BK=16, 256 thr (8 warps),
// warp tile 64(m) x 32(n) = 4 m16-tiles x 4 n8-tiles.
// mode 0: A = x, scatter C into g_Q/g_K/g_V (Q scaled). mode 1: A = g_O -> out.
// ---------------------------------------------------------------------------
__global__ __launch_bounds__(256, 2)
void gemm_tf32_kernel(const float* __restrict__ A, const float* __restrict__ Bw,
                      float* __restrict__ out, int M, int N, int K, int mode)
{
    __shared__ uint32_t As[16][132];   // As[k][m], tf32 bits
    __shared__ uint32_t Bs[16][132];   // Bs[k][n]

    const float* __restrict__ Ap = (mode == 1) ? (const float*)g_O : A;

    const int m0 = blockIdx.y * 128, n0 = blockIdx.x * 128;
    const int tid = threadIdx.x;
    const int warp = tid >> 5, lane = tid & 31;
    const int wy = warp >> 2, wx = warp & 3;      // 2 x 4 warp grid
    const int qr = lane >> 2, qc = lane & 3;      // groupID, threadID_in_group

    float acc[4][4][4];
#pragma unroll
    for (int i = 0; i < 4; i++)
#pragma unroll
        for (int j = 0; j < 4; j++)
#pragma unroll
            for (int r = 0; r < 4; r++) acc[i][j][r] = 0.0f;

    for (int k0 = 0; k0 < K; k0 += 16) {
        __syncthreads();
#pragma unroll
        for (int i = 0; i < 2; i++) {
            int v  = tid + i * 256;     // 0..511
            int r  = v >> 2;            // 0..127
            int c4 = (v & 3) * 4;       // 0,4,8,12
            float4 av = *(const float4*)(Ap + (size_t)(m0 + r) * K + k0 + c4);
            As[c4 + 0][r] = f2tf(av.x); As[c4 + 1][r] = f2tf(av.y);
            As[c4 + 2][r] = f2tf(av.z); As[c4 + 3][r] = f2tf(av.w);
            float4 bv = *(const float4*)(Bw + (size_t)(n0 + r) * K + k0 + c4);
            Bs[c4 + 0][r] = f2tf(bv.x); Bs[c4 + 1][r] = f2tf(bv.y);
            Bs[c4 + 2][r] = f2tf(bv.z); Bs[c4 + 3][r] = f2tf(bv.w);
        }
        __syncthreads();

#pragma unroll
        for (int kk = 0; kk < 2; kk++) {
            const int kb = kk * 8;
            uint32_t bb[4][2];
#pragma unroll
            for (int j = 0; j < 4; j++) {
                int nc = wx * 32 + j * 8 + qr;
                bb[j][0] = Bs[kb + qc][nc];
                bb[j][1] = Bs[kb + qc + 4][nc];
            }
#pragma unroll
            for (int i = 0; i < 4; i++) {
                int mr = wy * 64 + i * 16 + qr;
                uint32_t a0 = As[kb + qc][mr];
                uint32_t a1 = As[kb + qc][mr + 8];
                uint32_t a2 = As[kb + qc + 4][mr];
                uint32_t a3 = As[kb + qc + 4][mr + 8];
#pragma unroll
                for (int j = 0; j < 4; j++)
                    mma8(acc[i][j], a0, a1, a2, a3, bb[j][0], bb[j][1]);
            }
        }
    }

    // Epilogue: C frag (r=qr rows, cols 2*qc+{0,1})
#pragma unroll
    for (int i = 0; i < 4; i++) {
#pragma unroll
        for (int j = 0; j < 4; j++) {
            int mA = m0 + wy * 64 + i * 16 + qr;
            int nA = n0 + wx * 32 + j * 8 + qc * 2;
            if (mode == 0) {
                qkv_scatter(mA,     nA,     acc[i][j][0]);
                qkv_scatter(mA,     nA + 1, acc[i][j][1]);
                qkv_scatter(mA + 8, nA,     acc[i][j][2]);
                qkv_scatter(mA + 8, nA + 1, acc[i][j][3]);
            } else {
                *(float2*)(out + (size_t)mA * N + nA)
                    = make_float2(acc[i][j][0], acc[i][j][1]);
                *(float2*)(out + (size_t)(mA + 8) * N + nA)
                    = make_float2(acc[i][j][2], acc[i][j][3]);
            }
        }
    }
}

// ---------------------------------------------------------------------------
// Flash attention, tf32 mma. One block per (bh, 128-q-row tile). Bc=64.
// 8 warps; warp w owns q-rows 16w..16w+15 (one m16 across all 64 keys / dims).
// SMEM (uint32 tf32): Qs[128][68] | Ks[64][68] | Vs[64][68] | Ps[128][68]
// ---------------------------------------------------------------------------
#define AK_OFF (128 * 68)
#define AV_OFF (128 * 68 + 64 * 68)
#define AP_OFF (128 * 68 + 2 * 64 * 68)
#define A_SMEM_BYTES ((128 * 68 * 2 + 64 * 68 * 2) * 4)   // 104448

__global__ __launch_bounds__(256, 2)
void attn_tf32_kernel()
{
    extern __shared__ uint32_t sm[];
    uint32_t* Qs = sm;
    uint32_t* Ks = sm + AK_OFF;
    uint32_t* Vs = sm + AV_OFF;
    uint32_t* Ps = sm + AP_OFF;

    const int qt = blockIdx.x;          // 0..15
    const int bh = blockIdx.y;          // 0..63
    const float* __restrict__ Qg = g_Q + (size_t)bh * (T_ * DK_) + (size_t)qt * (128 * DK_);
    const float* __restrict__ Kg = g_K + (size_t)bh * (T_ * DK_);
    const float* __restrict__ Vg = g_V + (size_t)bh * (T_ * DK_);

    const int tid = threadIdx.x, warp = tid >> 5, lane = tid & 31;
    const int qr = lane >> 2, qc = lane & 3;
    const int wrow = warp * 16;

    // Load Q tile (128x64) once, tf32
#pragma unroll
    for (int i = 0; i < 8; i++) {
        int v = tid + i * 256, r = v >> 4, c4 = (v & 15) * 4;
        float4 qv = *(const float4*)(Qg + r * 64 + c4);
        Qs[r * 68 + c4 + 0] = f2tf(qv.x); Qs[r * 68 + c4 + 1] = f2tf(qv.y);
        Qs[r * 68 + c4 + 2] = f2tf(qv.z); Qs[r * 68 + c4 + 3] = f2tf(qv.w);
    }

    float o[8][4];
#pragma unroll
    for (int j = 0; j < 8; j++)
#pragma unroll
        for (int r = 0; r < 4; r++) o[j][r] = 0.0f;
    float m0r = -1e30f, m1r = -1e30f, l0 = 0.0f, l1 = 0.0f;

    for (int kt = 0; kt < T_ / 64; kt++) {
        __syncthreads();                 // prior PV reads of Vs done
#pragma unroll
        for (int i = 0; i < 4; i++) {
            int v = tid + i * 256, r = v >> 4, c4 = (v & 15) * 4;
            float4 kv = *(const float4*)(Kg + kt * 4096 + r * 64 + c4);
            Ks[r * 68 + c4 + 0] = f2tf(kv.x); Ks[r * 68 + c4 + 1] = f2tf(kv.y);
            Ks[r * 68 + c4 + 2] = f2tf(kv.z); Ks[r * 68 + c4 + 3] = f2tf(kv.w);
            float4 vv = *(const float4*)(Vg + kt * 4096 + r * 64 + c4);
            Vs[r * 68 + c4 + 0] = f2tf(vv.x); Vs[r * 68 + c4 + 1] = f2tf(vv.y);
            Vs[r * 68 + c4 + 2] = f2tf(vv.z); Vs[r * 68 + c4 + 3] = f2tf(vv.w);
        }
        __syncthreads();

        // S[16 x 64] = Q @ K^T : A=Q(row), B(k=d, n=key)=Ks[key][d]
        float s[8][4];
#pragma unroll
        for (int j = 0; j < 8; j++)
#pragma unroll
            for (int r = 0; r < 4; r++) s[j][r] = 0.0f;
#pragma unroll
        for (int kk = 0; kk < 8; kk++) {
            const int kb = kk * 8;
            uint32_t a0 = Qs[(wrow + qr) * 68 + kb + qc];
            uint32_t a1 = Qs[(wrow + qr + 8) * 68 + kb + qc];
            uint32_t a2 = Qs[(wrow + qr) * 68 + kb + qc + 4];
            uint32_t a3 = Qs[(wrow + qr + 8) * 68 + kb + qc + 4];
#pragma unroll
            for (int j = 0; j < 8; j++) {
                uint32_t b0 = Ks[(j * 8 + qr) * 68 + kb + qc];
                uint32_t b1 = Ks[(j * 8 + qr) * 68 + kb + qc + 4];
                mma8(s[j], a0, a1, a2, a3, b0, b1);
            }
        }

        // Online softmax: thread owns rows (wrow+qr) and (wrow+qr+8),
        // 16 cols per row spread over quad (shfl_xor 1,2 reduces the row).
        float v0 = -1e30f, v1 = -1e30f;
#pragma unroll
        for (int j = 0; j < 8; j++) {
            v0 = fmaxf(v0, fmaxf(s[j][0], s[j][1]));
            v1 = fmaxf(v1, fmaxf(s[j][2], s[j][3]));
        }
        v0 = fmaxf(v0, __shfl_xor_sync(0xffffffffu, v0, 1));
        v0 = fmaxf(v0, __shfl_xor_sync(0xffffffffu, v0, 2));
        v1 = fmaxf(v1, __shfl_xor_sync(0xffffffffu, v1, 1));
        v1 = fmaxf(v1, __shfl_xor_sync(0xffffffffu, v1, 2));
        float mn0 = fmaxf(m0r, v0), mn1 = fmaxf(m1r, v1);
        float al0 = __expf(m0r - mn0), al1 = __expf(m1r - mn1);
        m0r = mn0; m1r = mn1;

        float rs0 = 0.0f, rs1 = 0.0f;
#pragma unroll
        for (int j = 0; j < 8; j++) {
            float p0 = __expf(s[j][0] - mn0), p1 = __expf(s[j][1] - mn0);
            float p2 = __expf(s[j][2] - mn1), p3 = __expf(s[j][3] - mn1);
            rs0 += p0 + p1; rs1 += p2 + p3;
            int col = j * 8 + qc * 2;
            Ps[(wrow + qr) * 68 + col]         = f2tf(p0);
            Ps[(wrow + qr) * 68 + col + 1]     = f2tf(p1);
            Ps[(wrow + qr + 8) * 68 + col]     = f2tf(p2);
            Ps[(wrow + qr + 8) * 68 + col + 1] = f2tf(p3);
            o[j][0] *= al0; o[j][1] *= al0; o[j][2] *= al1; o[j][3] *= al1;
        }
        rs0 += __shfl_xor_sync(0xffffffffu, rs0, 1);
        rs0 += __shfl_xor_sync(0xffffffffu, rs0, 2);
        rs1 += __shfl_xor_sync(0xffffffffu, rs1, 1);
        rs1 += __shfl_xor_sync(0xffffffffu, rs1, 2);
        l0 = l0 * al0 + rs0;
        l1 = l1 * al1 + rs1;
        __syncwarp();   // Ps visible within warp (only own rows are read)

        // O[16 x 64] += P @ V : A=P(row, k=key), B(k=key, n=d)=Vs[key][d]
#pragma unroll
        for (int kk = 0; kk < 8; kk++) {
            const int kb = kk * 8;
            uint32_t a0 = Ps[(wrow + qr) * 68 + kb + qc];
            uint32_t a1 = Ps[(wrow + qr + 8) * 68 + kb + qc];
            uint32_t a2 = Ps[(wrow + qr) * 68 + kb + qc + 4];
            uint32_t a3 = Ps[(wrow + qr + 8) * 68 + kb + qc + 4];
#pragma unroll
            for (int j = 0; j < 8; j++) {
                uint32_t b0 = Vs[(kb + qc) * 68 + j * 8 + qr];
                uint32_t b1 = Vs[(kb + qc + 4) * 68 + j * 8 + qr];
                mma8(o[j], a0, a1, a2, a3, b0, b1);
            }
        }
    }

    // Normalize and store to g_O [B,T,D]
    const int b = bh >> 4, h = bh & 15;
    const float inv0 = 1.0f / l0, inv1 = 1.0f / l1;
    const int t0 = qt * 128 + wrow + qr;
#pragma unroll
    for (int j = 0; j < 8; j++) {
        int dcol = h * 64 + j * 8 + qc * 2;
        *(float2*)&g_O[((size_t)(b * T_ + t0)) * D_ + dcol]
            = make_float2(o[j][0] * inv0, o[j][1] * inv0);
        *(float2*)&g_O[((size_t)(b * T_ + t0 + 8)) * D_ + dcol]
            = make_float2(o[j][2] * inv1, o[j][3] * inv1);
    }
}

// ---------------------------------------------------------------------------
extern "C" void kernel_launch(void* const* d_in, const int* in_sizes, int n_in,
                              void* d_out, int out_size)
{
    const float* x      = (const float*)d_in[0];   // [4,2048,1024]
    const float* W_qkv  = (const float*)d_in[1];   // [3072,1024]
    const float* W_proj = (const float*)d_in[2];   // [1024,1024]
    float* out = (float*)d_out;                    // [4,2048,1024]

    cudaFuncSetAttribute(attn_tf32_kernel,
                         cudaFuncAttributeMaxDynamicSharedMemorySize,
                         A_SMEM_BYTES);

    // 1) QKV GEMM + head-layout scatter (Q pre-scaled)
    dim3 g1(3 * D_ / 128, M_ / 128);   // (24, 64)
    gemm_tf32_kernel<<<g1, 256>>>(x, W_qkv, nullptr, M_, 3 * D_, D_, 0);

    // 2) Flash attention
    dim3 g2(T_ / 128, B_ * H_);        // (16, 64)
    attn_tf32_kernel<<<g2, 256, A_SMEM_BYTES>>>();

    // 3) Output projection
    dim3 g3(D_ / 128, M_ / 128);       // (8, 64)
    gemm_tf32_kernel<<<g3, 256>>>(nullptr, W_proj, out, M_, D_, D_, 1);
}

// round 15
// speedup vs baseline: 2.5679x; 1.1463x over previous
#include <cuda_runtime.h>
#include <cuda_bf16.h>
#include <cstdint>

// ---------------------------------------------------------------------------
// MHA via tf32 mma.sync (m16n8k8) everywhere.
// x[4,2048,1024] -> QKV gemm -> 16-head flash attention -> proj gemm
// GEMM: CTA 128x256, warp tile 64x64, paired-k float2 SMEM, double-buffered.
// ---------------------------------------------------------------------------

#define B_   4
#define T_   2048
#define D_   1024
#define H_   16
#define DK_  64
#define M_   (B_ * T_)          // 8192

// Scratch (allocation-free rule: __device__ globals)
__device__ float g_Q[B_ * H_ * T_ * DK_];   // pre-scaled by 1/sqrt(dk)
__device__ float g_K[B_ * H_ * T_ * DK_];
__device__ float g_V[B_ * H_ * T_ * DK_];
__device__ float g_O[B_ * T_ * D_];         // attention output, [B,T,D]

__device__ __forceinline__ uint32_t f2tf(float f) {
    uint32_t u; asm("cvt.rna.tf32.f32 %0, %1;" : "=r"(u) : "f"(f)); return u;
}

// D = A(16x8,row) * B(8x8,col) + D, tf32 in / f32 out
__device__ __forceinline__ void mma8(float c[4],
                                     uint32_t a0, uint32_t a1, uint32_t a2, uint32_t a3,
                                     uint32_t b0, uint32_t b1) {
    asm volatile("mma.sync.aligned.m16n8k8.row.col.f32.tf32.tf32.f32 "
                 "{%0,%1,%2,%3}, {%4,%5,%6,%7}, {%8,%9}, {%0,%1,%2,%3};"
                 : "+f"(c[0]), "+f"(c[1]), "+f"(c[2]), "+f"(c[3])
                 : "r"(a0), "r"(a1), "r"(a2), "r"(a3), "r"(b0), "r"(b1));
}

__device__ __forceinline__ void qkv_scatter(int m, int n, float c) {
    int b = m >> 11, t = m & 2047;
    int which = n >> 10, rem = n & 1023;
    int h = rem >> 6, dd = rem & 63;
    size_t idx = ((size_t)((b << 4) + h) * T_ + t) * DK_ + dd;
    if (which == 0)      g_Q[idx] = c * 0.125f;    // 1/sqrt(64)
    else if (which == 1) g_K[idx] = c;
    else                 g_V[idx] = c;
}

// ---------------------------------------------------------------------------
// TN GEMM: C[M,N] = A[M,K] @ Bw[N,K]^T
// BM=128, BN=256, BK=16, 256 thr (8 warps, 2x4), warp tile 64x64.
// SMEM paired-k layout, float2 units:
//   A: plane p = kk*4+q (8 planes), Af2[p][m], pitch GMP=132
//      Af2[p][m] = { tf32 A[m][kb+q], tf32 A[m][kb+q+4] },  kb = kk*8
//   B: same with Bf2[p][n], pitch GNP=260
// A tile = 128 rows -> TWO 256-thread passes (this was the R13 bug: only one).
// B tile = 256 rows -> four passes. Double buffered (x2).
// mode 0: scatter QKV (Q scaled). mode 1: g_O -> out.
// ---------------------------------------------------------------------------
#define GMP 132
#define GNP 260
#define GA_F2 (8 * GMP)                 // float2 per A buffer
#define GB_F2 (8 * GNP)
#define GEMM_SMEM_BYTES ((2 * GA_F2 + 2 * GB_F2) * 8)   // 50176

__device__ __forceinline__ void st_paired(float2* base, int pitch, int r, int c4,
                                          float4 v) {
    int pb = (c4 >= 8) ? 4 : 0;
    int h  = (c4 & 4) ? 1 : 0;
    float* w = (float*)(base + (size_t)pb * pitch + r);
    w[h]             = __uint_as_float(f2tf(v.x));
    w[2 * pitch + h] = __uint_as_float(f2tf(v.y));
    w[4 * pitch + h] = __uint_as_float(f2tf(v.z));
    w[6 * pitch + h] = __uint_as_float(f2tf(v.w));
}

__global__ __launch_bounds__(256, 1)
void gemm_tf32_kernel(const float* __restrict__ A, const float* __restrict__ Bw,
                      float* __restrict__ out, int M, int N, int K, int mode)
{
    extern __shared__ float2 smf2[];
    float2* Af2 = smf2;                 // [2][8][GMP]
    float2* Bf2 = smf2 + 2 * GA_F2;     // [2][8][GNP]

    const float* __restrict__ Ap = (mode == 1) ? (const float*)g_O : A;

    const int m0 = blockIdx.y * 128, n0 = blockIdx.x * 256;
    const int tid = threadIdx.x;
    const int warp = tid >> 5, lane = tid & 31;
    const int wy = warp >> 2, wx = warp & 3;      // 2 x 4 warp grid
    const int qr = lane >> 2, qc = lane & 3;

    const int lr  = tid >> 2;                     // load row (pass adds +64/+128/..)
    const int lc4 = (tid & 3) * 4;                // load k-offset (0,4,8,12)

    float acc[4][8][4];
#pragma unroll
    for (int i = 0; i < 4; i++)
#pragma unroll
        for (int j = 0; j < 8; j++)
#pragma unroll
            for (int r = 0; r < 4; r++) acc[i][j][r] = 0.0f;

    // ---- prologue: load k-block 0 into buffer 0 ----
#pragma unroll
    for (int i = 0; i < 2; i++) {
        float4 av = *(const float4*)(Ap + (size_t)(m0 + lr + i * 64) * K + lc4);
        st_paired(Af2, GMP, lr + i * 64, lc4, av);
    }
#pragma unroll
    for (int i = 0; i < 4; i++) {
        float4 bv = *(const float4*)(Bw + (size_t)(n0 + lr + i * 64) * K + lc4);
        st_paired(Bf2, GNP, lr + i * 64, lc4, bv);
    }
    __syncthreads();

    for (int k0 = 0; k0 < K; k0 += 16) {
        const int buf = (k0 >> 4) & 1;
        const float2* Ab = Af2 + (size_t)buf * GA_F2;
        const float2* Bb = Bf2 + (size_t)buf * GB_F2;
        const bool more = (k0 + 16) < K;

        // prefetch next k-block into registers
        float4 pa[2], pb[4];
        if (more) {
#pragma unroll
            for (int i = 0; i < 2; i++)
                pa[i] = *(const float4*)(Ap + (size_t)(m0 + lr + i * 64) * K + k0 + 16 + lc4);
#pragma unroll
            for (int i = 0; i < 4; i++)
                pb[i] = *(const float4*)(Bw + (size_t)(n0 + lr + i * 64) * K + k0 + 16 + lc4);
        }

        // ---- compute 2 kk-steps from current buffer ----
#pragma unroll
        for (int kk = 0; kk < 2; kk++) {
            const float2* apl = Ab + (size_t)(kk * 4 + qc) * GMP;
            const float2* bpl = Bb + (size_t)(kk * 4 + qc) * GNP;
            uint32_t afr[4][4];
#pragma unroll
            for (int i = 0; i < 4; i++) {
                int mr = wy * 64 + i * 16 + qr;
                float2 lo = apl[mr];
                float2 hi = apl[mr + 8];
                afr[i][0] = __float_as_uint(lo.x);   // (m,   kb+qc)
                afr[i][1] = __float_as_uint(hi.x);   // (m+8, kb+qc)
                afr[i][2] = __float_as_uint(lo.y);   // (m,   kb+qc+4)
                afr[i][3] = __float_as_uint(hi.y);   // (m+8, kb+qc+4)
            }
            uint32_t bfr[8][2];
#pragma unroll
            for (int j = 0; j < 8; j++) {
                float2 bv = bpl[wx * 64 + j * 8 + qr];
                bfr[j][0] = __float_as_uint(bv.x);
                bfr[j][1] = __float_as_uint(bv.y);
            }
#pragma unroll
            for (int i = 0; i < 4; i++)
#pragma unroll
                for (int j = 0; j < 8; j++)
                    mma8(acc[i][j], afr[i][0], afr[i][1], afr[i][2], afr[i][3],
                         bfr[j][0], bfr[j][1]);
        }

        // ---- store prefetched block into the other buffer ----
        if (more) {
            float2* An = Af2 + (size_t)(buf ^ 1) * GA_F2;
            float2* Bn = Bf2 + (size_t)(buf ^ 1) * GB_F2;
#pragma unroll
            for (int i = 0; i < 2; i++)
                st_paired(An, GMP, lr + i * 64, lc4, pa[i]);
#pragma unroll
            for (int i = 0; i < 4; i++)
                st_paired(Bn, GNP, lr + i * 64, lc4, pb[i]);
        }
        __syncthreads();
    }

    // ---- epilogue ----
#pragma unroll
    for (int i = 0; i < 4; i++) {
#pragma unroll
        for (int j = 0; j < 8; j++) {
            int mA = m0 + wy * 64 + i * 16 + qr;
            int nA = n0 + wx * 64 + j * 8 + qc * 2;
            if (mode == 0) {
                qkv_scatter(mA,     nA,     acc[i][j][0]);
                qkv_scatter(mA,     nA + 1, acc[i][j][1]);
                qkv_scatter(mA + 8, nA,     acc[i][j][2]);
                qkv_scatter(mA + 8, nA + 1, acc[i][j][3]);
            } else {
                *(float2*)(out + (size_t)mA * N + nA)
                    = make_float2(acc[i][j][0], acc[i][j][1]);
                *(float2*)(out + (size_t)(mA + 8) * N + nA)
                    = make_float2(acc[i][j][2], acc[i][j][3]);
            }
        }
    }
}

// ---------------------------------------------------------------------------
// Flash attention, tf32 mma (unchanged from passing R12 version).
// One block per (bh, 128-q-row tile). Bc=64. 8 warps; warp w owns q-rows
// 16w..16w+15. SMEM (uint32 tf32): Qs[128][68] | Ks[64][68] | Vs[64][68] | Ps[128][68]
// ---------------------------------------------------------------------------
#define AK_OFF (128 * 68)
#define AV_OFF (128 * 68 + 64 * 68)
#define AP_OFF (128 * 68 + 2 * 64 * 68)
#define A_SMEM_BYTES ((128 * 68 * 2 + 64 * 68 * 2) * 4)   // 104448

__global__ __launch_bounds__(256, 2)
void attn_tf32_kernel()
{
    extern __shared__ uint32_t sm[];
    uint32_t* Qs = sm;
    uint32_t* Ks = sm + AK_OFF;
    uint32_t* Vs = sm + AV_OFF;
    uint32_t* Ps = sm + AP_OFF;

    const int qt = blockIdx.x;          // 0..15
    const int bh = blockIdx.y;          // 0..63
    const float* __restrict__ Qg = g_Q + (size_t)bh * (T_ * DK_) + (size_t)qt * (128 * DK_);
    const float* __restrict__ Kg = g_K + (size_t)bh * (T_ * DK_);
    const float* __restrict__ Vg = g_V + (size_t)bh * (T_ * DK_);

    const int tid = threadIdx.x, warp = tid >> 5, lane = tid & 31;
    const int qr = lane >> 2, qc = lane & 3;
    const int wrow = warp * 16;

#pragma unroll
    for (int i = 0; i < 8; i++) {
        int v = tid + i * 256, r = v >> 4, c4 = (v & 15) * 4;
        float4 qv = *(const float4*)(Qg + r * 64 + c4);
        Qs[r * 68 + c4 + 0] = f2tf(qv.x); Qs[r * 68 + c4 + 1] = f2tf(qv.y);
        Qs[r * 68 + c4 + 2] = f2tf(qv.z); Qs[r * 68 + c4 + 3] = f2tf(qv.w);
    }

    float o[8][4];
#pragma unroll
    for (int j = 0; j < 8; j++)
#pragma unroll
        for (int r = 0; r < 4; r++) o[j][r] = 0.0f;
    float m0r = -1e30f, m1r = -1e30f, l0 = 0.0f, l1 = 0.0f;

    for (int kt = 0; kt < T_ / 64; kt++) {
        __syncthreads();
#pragma unroll
        for (int i = 0; i < 4; i++) {
            int v = tid + i * 256, r = v >> 4, c4 = (v & 15) * 4;
            float4 kv = *(const float4*)(Kg + kt * 4096 + r * 64 + c4);
            Ks[r * 68 + c4 + 0] = f2tf(kv.x); Ks[r * 68 + c4 + 1] = f2tf(kv.y);
            Ks[r * 68 + c4 + 2] = f2tf(kv.z); Ks[r * 68 + c4 + 3] = f2tf(kv.w);
            float4 vv = *(const float4*)(Vg + kt * 4096 + r * 64 + c4);
            Vs[r * 68 + c4 + 0] = f2tf(vv.x); Vs[r * 68 + c4 + 1] = f2tf(vv.y);
            Vs[r * 68 + c4 + 2] = f2tf(vv.z); Vs[r * 68 + c4 + 3] = f2tf(vv.w);
        }
        __syncthreads();

        float s[8][4];
#pragma unroll
        for (int j = 0; j < 8; j++)
#pragma unroll
            for (int r = 0; r < 4; r++) s[j][r] = 0.0f;
#pragma unroll
        for (int kk = 0; kk < 8; kk++) {
            const int kb = kk * 8;
            uint32_t a0 = Qs[(wrow + qr) * 68 + kb + qc];
            uint32_t a1 = Qs[(wrow + qr + 8) * 68 + kb + qc];
            uint32_t a2 = Qs[(wrow + qr) * 68 + kb + qc + 4];
            uint32_t a3 = Qs[(wrow + qr + 8) * 68 + kb + qc + 4];
#pragma unroll
            for (int j = 0; j < 8; j++) {
                uint32_t b0 = Ks[(j * 8 + qr) * 68 + kb + qc];
                uint32_t b1 = Ks[(j * 8 + qr) * 68 + kb + qc + 4];
                mma8(s[j], a0, a1, a2, a3, b0, b1);
            }
        }

        float v0 = -1e30f, v1 = -1e30f;
#pragma unroll
        for (int j = 0; j < 8; j++) {
            v0 = fmaxf(v0, fmaxf(s[j][0], s[j][1]));
            v1 = fmaxf(v1, fmaxf(s[j][2], s[j][3]));
        }
        v0 = fmaxf(v0, __shfl_xor_sync(0xffffffffu, v0, 1));
        v0 = fmaxf(v0, __shfl_xor_sync(0xffffffffu, v0, 2));
        v1 = fmaxf(v1, __shfl_xor_sync(0xffffffffu, v1, 1));
        v1 = fmaxf(v1, __shfl_xor_sync(0xffffffffu, v1, 2));
        float mn0 = fmaxf(m0r, v0), mn1 = fmaxf(m1r, v1);
        float al0 = __expf(m0r - mn0), al1 = __expf(m1r - mn1);
        m0r = mn0; m1r = mn1;

        float rs0 = 0.0f, rs1 = 0.0f;
#pragma unroll
        for (int j = 0; j < 8; j++) {
            float p0 = __expf(s[j][0] - mn0), p1 = __expf(s[j][1] - mn0);
            float p2 = __expf(s[j][2] - mn1), p3 = __expf(s[j][3] - mn1);
            rs0 += p0 + p1; rs1 += p2 + p3;
            int col = j * 8 + qc * 2;
            Ps[(wrow + qr) * 68 + col]         = f2tf(p0);
            Ps[(wrow + qr) * 68 + col + 1]     = f2tf(p1);
            Ps[(wrow + qr + 8) * 68 + col]     = f2tf(p2);
            Ps[(wrow + qr + 8) * 68 + col + 1] = f2tf(p3);
            o[j][0] *= al0; o[j][1] *= al0; o[j][2] *= al1; o[j][3] *= al1;
        }
        rs0 += __shfl_xor_sync(0xffffffffu, rs0, 1);
        rs0 += __shfl_xor_sync(0xffffffffu, rs0, 2);
        rs1 += __shfl_xor_sync(0xffffffffu, rs1, 1);
        rs1 += __shfl_xor_sync(0xffffffffu, rs1, 2);
        l0 = l0 * al0 + rs0;
        l1 = l1 * al1 + rs1;
        __syncwarp();

#pragma unroll
        for (int kk = 0; kk < 8; kk++) {
            const int kb = kk * 8;
            uint32_t a0 = Ps[(wrow + qr) * 68 + kb + qc];
            uint32_t a1 = Ps[(wrow + qr + 8) * 68 + kb + qc];
            uint32_t a2 = Ps[(wrow + qr) * 68 + kb + qc + 4];
            uint32_t a3 = Ps[(wrow + qr + 8) * 68 + kb + qc + 4];
#pragma unroll
            for (int j = 0; j < 8; j++) {
                uint32_t b0 = Vs[(kb + qc) * 68 + j * 8 + qr];
                uint32_t b1 = Vs[(kb + qc + 4) * 68 + j * 8 + qr];
                mma8(o[j], a0, a1, a2, a3, b0, b1);
            }
        }
    }

    const int b = bh >> 4, h = bh & 15;
    const float inv0 = 1.0f / l0, inv1 = 1.0f / l1;
    const int t0 = qt * 128 + wrow + qr;
#pragma unroll
    for (int j = 0; j < 8; j++) {
        int dcol = h * 64 + j * 8 + qc * 2;
        *(float2*)&g_O[((size_t)(b * T_ + t0)) * D_ + dcol]
            = make_float2(o[j][0] * inv0, o[j][1] * inv0);
        *(float2*)&g_O[((size_t)(b * T_ + t0 + 8)) * D_ + dcol]
            = make_float2(o[j][2] * inv1, o[j][3] * inv1);
    }
}

// ---------------------------------------------------------------------------
extern "C" void kernel_launch(void* const* d_in, const int* in_sizes, int n_in,
                              void* d_out, int out_size)
{
    const float* x      = (const float*)d_in[0];   // [4,2048,1024]
    const float* W_qkv  = (const float*)d_in[1];   // [3072,1024]
    const float* W_proj = (const float*)d_in[2];   // [1024,1024]
    float* out = (float*)d_out;                    // [4,2048,1024]

    cudaFuncSetAttribute(gemm_tf32_kernel,
                         cudaFuncAttributeMaxDynamicSharedMemorySize,
                         GEMM_SMEM_BYTES);
    cudaFuncSetAttribute(attn_tf32_kernel,
                         cudaFuncAttributeMaxDynamicSharedMemorySize,
                         A_SMEM_BYTES);

    // 1) QKV GEMM + head-layout scatter (Q pre-scaled)
    dim3 g1(3 * D_ / 256, M_ / 128);   // (12, 64)
    gemm_tf32_kernel<<<g1, 256, GEMM_SMEM_BYTES>>>(x, W_qkv, nullptr, M_, 3 * D_, D_, 0);

    // 2) Flash attention
    dim3 g2(T_ / 128, B_ * H_);        // (16, 64)
    attn_tf32_kernel<<<g2, 256, A_SMEM_BYTES>>>();

    // 3) Output projection
    dim3 g3(D_ / 256, M_ / 128);       // (4, 64)
    gemm_tf32_kernel<<<g3, 256, GEMM_SMEM_BYTES>>>(nullptr, W_proj, out, M_, D_, D_, 1);
}

// round 16
// speedup vs baseline: 2.6024x; 1.0134x over previous
#include <cuda_runtime.h>
#include <cuda_bf16.h>
#include <cstdint>

// ---------------------------------------------------------------------------
// MHA via tf32 mma.sync (m16n8k8) everywhere.
// x[4,2048,1024] -> QKV gemm -> 16-head flash attention -> proj gemm
// GEMM: CTA 128x256, 512 thr (16 warps), warp tile 64x32, paired-k float2
//       SMEM, double-buffered.  (R14 had 8 warps -> latency-bound, occ 12.5%)
// ---------------------------------------------------------------------------

#define B_   4
#define T_   2048
#define D_   1024
#define H_   16
#define DK_  64
#define M_   (B_ * T_)          // 8192

// Scratch (allocation-free rule: __device__ globals)
__device__ float g_Q[B_ * H_ * T_ * DK_];   // pre-scaled by 1/sqrt(dk)
__device__ float g_K[B_ * H_ * T_ * DK_];
__device__ float g_V[B_ * H_ * T_ * DK_];
__device__ float g_O[B_ * T_ * D_];         // attention output, [B,T,D]

__device__ __forceinline__ uint32_t f2tf(float f) {
    uint32_t u; asm("cvt.rna.tf32.f32 %0, %1;" : "=r"(u) : "f"(f)); return u;
}

// D = A(16x8,row) * B(8x8,col) + D, tf32 in / f32 out
__device__ __forceinline__ void mma8(float c[4],
                                     uint32_t a0, uint32_t a1, uint32_t a2, uint32_t a3,
                                     uint32_t b0, uint32_t b1) {
    asm volatile("mma.sync.aligned.m16n8k8.row.col.f32.tf32.tf32.f32 "
                 "{%0,%1,%2,%3}, {%4,%5,%6,%7}, {%8,%9}, {%0,%1,%2,%3};"
                 : "+f"(c[0]), "+f"(c[1]), "+f"(c[2]), "+f"(c[3])
                 : "r"(a0), "r"(a1), "r"(a2), "r"(a3), "r"(b0), "r"(b1));
}

__device__ __forceinline__ void qkv_scatter(int m, int n, float c) {
    int b = m >> 11, t = m & 2047;
    int which = n >> 10, rem = n & 1023;
    int h = rem >> 6, dd = rem & 63;
    size_t idx = ((size_t)((b << 4) + h) * T_ + t) * DK_ + dd;
    if (which == 0)      g_Q[idx] = c * 0.125f;    // 1/sqrt(64)
    else if (which == 1) g_K[idx] = c;
    else                 g_V[idx] = c;
}

// ---------------------------------------------------------------------------
// TN GEMM: C[M,N] = A[M,K] @ Bw[N,K]^T
// BM=128, BN=256, BK=16, 512 thr (16 warps, 2x8), warp tile 64x32.
// SMEM paired-k layout, float2 units:
//   A: plane p = kk*4+q (8 planes), Af2[p][m], pitch GMP=132
//      Af2[p][m] = { tf32 A[m][kb+q], tf32 A[m][kb+q+4] },  kb = kk*8
//   B: same with Bf2[p][n], pitch GNP=260
// A tile = 128 rows -> ONE 512-thread pass; B tile = 256 rows -> two passes.
// Double buffered (x2). mode 0: scatter QKV (Q scaled). mode 1: g_O -> out.
// ---------------------------------------------------------------------------
#define GMP 132
#define GNP 260
#define GA_F2 (8 * GMP)                 // float2 per A buffer
#define GB_F2 (8 * GNP)
#define GEMM_SMEM_BYTES ((2 * GA_F2 + 2 * GB_F2) * 8)   // 50176

__device__ __forceinline__ void st_paired(float2* base, int pitch, int r, int c4,
                                          float4 v) {
    int pb = (c4 >> 3) * 4;
    int h  = (c4 & 4) ? 1 : 0;
    float* w = (float*)(base + (size_t)pb * pitch + r);
    w[h]             = __uint_as_float(f2tf(v.x));
    w[2 * pitch + h] = __uint_as_float(f2tf(v.y));
    w[4 * pitch + h] = __uint_as_float(f2tf(v.z));
    w[6 * pitch + h] = __uint_as_float(f2tf(v.w));
}

__global__ __launch_bounds__(512, 1)
void gemm_tf32_kernel(const float* __restrict__ A, const float* __restrict__ Bw,
                      float* __restrict__ out, int M, int N, int K, int mode)
{
    extern __shared__ float2 smf2[];
    float2* Af2 = smf2;                 // [2][8][GMP]
    float2* Bf2 = smf2 + 2 * GA_F2;     // [2][8][GNP]

    const float* __restrict__ Ap = (mode == 1) ? (const float*)g_O : A;

    const int m0 = blockIdx.y * 128, n0 = blockIdx.x * 256;
    const int tid = threadIdx.x;
    const int warp = tid >> 5, lane = tid & 31;
    const int wy = warp >> 3, wx = warp & 7;      // 2 x 8 warp grid
    const int qr = lane >> 2, qc = lane & 3;

    const int lr  = tid >> 2;                     // load row: 0..127
    const int lc4 = (tid & 3) * 4;                // load k-offset (0,4,8,12)

    float acc[4][4][4];
#pragma unroll
    for (int i = 0; i < 4; i++)
#pragma unroll
        for (int j = 0; j < 4; j++)
#pragma unroll
            for (int r = 0; r < 4; r++) acc[i][j][r] = 0.0f;

    // ---- prologue: load k-block 0 into buffer 0 ----
    {
        float4 av = *(const float4*)(Ap + (size_t)(m0 + lr) * K + lc4);
        st_paired(Af2, GMP, lr, lc4, av);
#pragma unroll
        for (int i = 0; i < 2; i++) {
            float4 bv = *(const float4*)(Bw + (size_t)(n0 + lr + i * 128) * K + lc4);
            st_paired(Bf2, GNP, lr + i * 128, lc4, bv);
        }
    }
    __syncthreads();

    for (int k0 = 0; k0 < K; k0 += 16) {
        const int buf = (k0 >> 4) & 1;
        const float2* Ab = Af2 + (size_t)buf * GA_F2;
        const float2* Bb = Bf2 + (size_t)buf * GB_F2;
        const bool more = (k0 + 16) < K;

        // prefetch next k-block into registers
        float4 pa, pb[2];
        if (more) {
            pa = *(const float4*)(Ap + (size_t)(m0 + lr) * K + k0 + 16 + lc4);
#pragma unroll
            for (int i = 0; i < 2; i++)
                pb[i] = *(const float4*)(Bw + (size_t)(n0 + lr + i * 128) * K + k0 + 16 + lc4);
        }

        // ---- compute 2 kk-steps from current buffer ----
#pragma unroll
        for (int kk = 0; kk < 2; kk++) {
            const float2* apl = Ab + (size_t)(kk * 4 + qc) * GMP;
            const float2* bpl = Bb + (size_t)(kk * 4 + qc) * GNP;
            uint32_t afr[4][4];
#pragma unroll
            for (int i = 0; i < 4; i++) {
                int mr = wy * 64 + i * 16 + qr;
                float2 lo = apl[mr];
                float2 hi = apl[mr + 8];
                afr[i][0] = __float_as_uint(lo.x);   // (m,   kb+qc)
                afr[i][1] = __float_as_uint(hi.x);   // (m+8, kb+qc)
                afr[i][2] = __float_as_uint(lo.y);   // (m,   kb+qc+4)
                afr[i][3] = __float_as_uint(hi.y);   // (m+8, kb+qc+4)
            }
            uint32_t bfr[4][2];
#pragma unroll
            for (int j = 0; j < 4; j++) {
                float2 bv = bpl[wx * 32 + j * 8 + qr];
                bfr[j][0] = __float_as_uint(bv.x);
                bfr[j][1] = __float_as_uint(bv.y);
            }
#pragma unroll
            for (int i = 0; i < 4; i++)
#pragma unroll
                for (int j = 0; j < 4; j++)
                    mma8(acc[i][j], afr[i][0], afr[i][1], afr[i][2], afr[i][3],
                         bfr[j][0], bfr[j][1]);
        }

        // ---- store prefetched block into the other buffer ----
        if (more) {
            float2* An = Af2 + (size_t)(buf ^ 1) * GA_F2;
            float2* Bn = Bf2 + (size_t)(buf ^ 1) * GB_F2;
            st_paired(An, GMP, lr, lc4, pa);
#pragma unroll
            for (int i = 0; i < 2; i++)
                st_paired(Bn, GNP, lr + i * 128, lc4, pb[i]);
        }
        __syncthreads();
    }

    // ---- epilogue ----
#pragma unroll
    for (int i = 0; i < 4; i++) {
#pragma unroll
        for (int j = 0; j < 4; j++) {
            int mA = m0 + wy * 64 + i * 16 + qr;
            int nA = n0 + wx * 32 + j * 8 + qc * 2;
            if (mode == 0) {
                qkv_scatter(mA,     nA,     acc[i][j][0]);
                qkv_scatter(mA,     nA + 1, acc[i][j][1]);
                qkv_scatter(mA + 8, nA,     acc[i][j][2]);
                qkv_scatter(mA + 8, nA + 1, acc[i][j][3]);
            } else {
                *(float2*)(out + (size_t)mA * N + nA)
                    = make_float2(acc[i][j][0], acc[i][j][1]);
                *(float2*)(out + (size_t)(mA + 8) * N + nA)
                    = make_float2(acc[i][j][2], acc[i][j][3]);
            }
        }
    }
}

// ---------------------------------------------------------------------------
// Flash attention, tf32 mma (unchanged from passing R12/R14 version).
// One block per (bh, 128-q-row tile). Bc=64. 8 warps; warp w owns q-rows
// 16w..16w+15. SMEM (uint32 tf32): Qs[128][68] | Ks[64][68] | Vs[64][68] | Ps[128][68]
// ---------------------------------------------------------------------------
#define AK_OFF (128 * 68)
#define AV_OFF (128 * 68 + 64 * 68)
#define AP_OFF (128 * 68 + 2 * 64 * 68)
#define A_SMEM_BYTES ((128 * 68 * 2 + 64 * 68 * 2) * 4)   // 104448

__global__ __launch_bounds__(256, 2)
void attn_tf32_kernel()
{
    extern __shared__ uint32_t sm[];
    uint32_t* Qs = sm;
    uint32_t* Ks = sm + AK_OFF;
    uint32_t* Vs = sm + AV_OFF;
    uint32_t* Ps = sm + AP_OFF;

    const int qt = blockIdx.x;          // 0..15
    const int bh = blockIdx.y;          // 0..63
    const float* __restrict__ Qg = g_Q + (size_t)bh * (T_ * DK_) + (size_t)qt * (128 * DK_);
    const float* __restrict__ Kg = g_K + (size_t)bh * (T_ * DK_);
    const float* __restrict__ Vg = g_V + (size_t)bh * (T_ * DK_);

    const int tid = threadIdx.x, warp = tid >> 5, lane = tid & 31;
    const int qr = lane >> 2, qc = lane & 3;
    const int wrow = warp * 16;

#pragma unroll
    for (int i = 0; i < 8; i++) {
        int v = tid + i * 256, r = v >> 4, c4 = (v & 15) * 4;
        float4 qv = *(const float4*)(Qg + r * 64 + c4);
        Qs[r * 68 + c4 + 0] = f2tf(qv.x); Qs[r * 68 + c4 + 1] = f2tf(qv.y);
        Qs[r * 68 + c4 + 2] = f2tf(qv.z); Qs[r * 68 + c4 + 3] = f2tf(qv.w);
    }

    float o[8][4];
#pragma unroll
    for (int j = 0; j < 8; j++)
#pragma unroll
        for (int r = 0; r < 4; r++) o[j][r] = 0.0f;
    float m0r = -1e30f, m1r = -1e30f, l0 = 0.0f, l1 = 0.0f;

    for (int kt = 0; kt < T_ / 64; kt++) {
        __syncthreads();
#pragma unroll
        for (int i = 0; i < 4; i++) {
            int v = tid + i * 256, r = v >> 4, c4 = (v & 15) * 4;
            float4 kv = *(const float4*)(Kg + kt * 4096 + r * 64 + c4);
            Ks[r * 68 + c4 + 0] = f2tf(kv.x); Ks[r * 68 + c4 + 1] = f2tf(kv.y);
            Ks[r * 68 + c4 + 2] = f2tf(kv.z); Ks[r * 68 + c4 + 3] = f2tf(kv.w);
            float4 vv = *(const float4*)(Vg + kt * 4096 + r * 64 + c4);
            Vs[r * 68 + c4 + 0] = f2tf(vv.x); Vs[r * 68 + c4 + 1] = f2tf(vv.y);
            Vs[r * 68 + c4 + 2] = f2tf(vv.z); Vs[r * 68 + c4 + 3] = f2tf(vv.w);
        }
        __syncthreads();

        float s[8][4];
#pragma unroll
        for (int j = 0; j < 8; j++)
#pragma unroll
            for (int r = 0; r < 4; r++) s[j][r] = 0.0f;
#pragma unroll
        for (int kk = 0; kk < 8; kk++) {
            const int kb = kk * 8;
            uint32_t a0 = Qs[(wrow + qr) * 68 + kb + qc];
            uint32_t a1 = Qs[(wrow + qr + 8) * 68 + kb + qc];
            uint32_t a2 = Qs[(wrow + qr) * 68 + kb + qc + 4];
            uint32_t a3 = Qs[(wrow + qr + 8) * 68 + kb + qc + 4];
#pragma unroll
            for (int j = 0; j < 8; j++) {
                uint32_t b0 = Ks[(j * 8 + qr) * 68 + kb + qc];
                uint32_t b1 = Ks[(j * 8 + qr) * 68 + kb + qc + 4];
                mma8(s[j], a0, a1, a2, a3, b0, b1);
            }
        }

        float v0 = -1e30f, v1 = -1e30f;
#pragma unroll
        for (int j = 0; j < 8; j++) {
            v0 = fmaxf(v0, fmaxf(s[j][0], s[j][1]));
            v1 = fmaxf(v1, fmaxf(s[j][2], s[j][3]));
        }
        v0 = fmaxf(v0, __shfl_xor_sync(0xffffffffu, v0, 1));
        v0 = fmaxf(v0, __shfl_xor_sync(0xffffffffu, v0, 2));
        v1 = fmaxf(v1, __shfl_xor_sync(0xffffffffu, v1, 1));
        v1 = fmaxf(v1, __shfl_xor_sync(0xffffffffu, v1, 2));
        float mn0 = fmaxf(m0r, v0), mn1 = fmaxf(m1r, v1);
        float al0 = __expf(m0r - mn0), al1 = __expf(m1r - mn1);
        m0r = mn0; m1r = mn1;

        float rs0 = 0.0f, rs1 = 0.0f;
#pragma unroll
        for (int j = 0; j < 8; j++) {
            float p0 = __expf(s[j][0] - mn0), p1 = __expf(s[j][1] - mn0);
            float p2 = __expf(s[j][2] - mn1), p3 = __expf(s[j][3] - mn1);
            rs0 += p0 + p1; rs1 += p2 + p3;
            int col = j * 8 + qc * 2;
            Ps[(wrow + qr) * 68 + col]         = f2tf(p0);
            Ps[(wrow + qr) * 68 + col + 1]     = f2tf(p1);
            Ps[(wrow + qr + 8) * 68 + col]     = f2tf(p2);
            Ps[(wrow + qr + 8) * 68 + col + 1] = f2tf(p3);
            o[j][0] *= al0; o[j][1] *= al0; o[j][2] *= al1; o[j][3] *= al1;
        }
        rs0 += __shfl_xor_sync(0xffffffffu, rs0, 1);
        rs0 += __shfl_xor_sync(0xffffffffu, rs0, 2);
        rs1 += __shfl_xor_sync(0xffffffffu, rs1, 1);
        rs1 += __shfl_xor_sync(0xffffffffu, rs1, 2);
        l0 = l0 * al0 + rs0;
        l1 = l1 * al1 + rs1;
        __syncwarp();

#pragma unroll
        for (int kk = 0; kk < 8; kk++) {
            const int kb = kk * 8;
            uint32_t a0 = Ps[(wrow + qr) * 68 + kb + qc];
            uint32_t a1 = Ps[(wrow + qr + 8) * 68 + kb + qc];
            uint32_t a2 = Ps[(wrow + qr) * 68 + kb + qc + 4];
            uint32_t a3 = Ps[(wrow + qr + 8) * 68 + kb + qc + 4];
#pragma unroll
            for (int j = 0; j < 8; j++) {
                uint32_t b0 = Vs[(kb + qc) * 68 + j * 8 + qr];
                uint32_t b1 = Vs[(kb + qc + 4) * 68 + j * 8 + qr];
                mma8(o[j], a0, a1, a2, a3, b0, b1);
            }
        }
    }

    const int b = bh >> 4, h = bh & 15;
    const float inv0 = 1.0f / l0, inv1 = 1.0f / l1;
    const int t0 = qt * 128 + wrow + qr;
#pragma unroll
    for (int j = 0; j < 8; j++) {
        int dcol = h * 64 + j * 8 + qc * 2;
        *(float2*)&g_O[((size_t)(b * T_ + t0)) * D_ + dcol]
            = make_float2(o[j][0] * inv0, o[j][1] * inv0);
        *(float2*)&g_O[((size_t)(b * T_ + t0 + 8)) * D_ + dcol]
            = make_float2(o[j][2] * inv1, o[j][3] * inv1);
    }
}

// ---------------------------------------------------------------------------
extern "C" void kernel_launch(void* const* d_in, const int* in_sizes, int n_in,
                              void* d_out, int out_size)
{
    const float* x      = (const float*)d_in[0];   // [4,2048,1024]
    const float* W_qkv  = (const float*)d_in[1];   // [3072,1024]
    const float* W_proj = (const float*)d_in[2];   // [1024,1024]
    float* out = (float*)d_out;                    // [4,2048,1024]

    cudaFuncSetAttribute(gemm_tf32_kernel,
                         cudaFuncAttributeMaxDynamicSharedMemorySize,
                         GEMM_SMEM_BYTES);
    cudaFuncSetAttribute(attn_tf32_kernel,
                         cudaFuncAttributeMaxDynamicSharedMemorySize,
                         A_SMEM_BYTES);

    // 1) QKV GEMM + head-layout scatter (Q pre-scaled)
    dim3 g1(3 * D_ / 256, M_ / 128);   // (12, 64)
    gemm_tf32_kernel<<<g1, 512, GEMM_SMEM_BYTES>>>(x, W_qkv, nullptr, M_, 3 * D_, D_, 0);

    // 2) Flash attention
    dim3 g2(T_ / 128, B_ * H_);        // (16, 64)
    attn_tf32_kernel<<<g2, 256, A_SMEM_BYTES>>>();

    // 3) Output projection
    dim3 g3(D_ / 256, M_ / 128);       // (4, 64)
    gemm_tf32_kernel<<<g3, 512, GEMM_SMEM_BYTES>>>(nullptr, W_proj, out, M_, D_, D_, 1);
}